// round 6
// baseline (speedup 1.0000x reference)
#include <cuda_runtime.h>
#include <math.h>

#define LEAKY 0.2f

// Scratch (allocation-free rule: __device__ globals)
__device__ float g_h[(size_t)8 * 8 * 1024 * 96];   // [b,h,n,o] fp32, 25.2 MB
__device__ float g_asrc[8 * 8 * 1024];             // [b,h,n]
__device__ float g_adst[8 * 8 * 1024];             // [b,h,n]

// ---------------------------------------------------------------------------
// Kernel 1: per-head projection GEMM h = feat_in @ W[h], plus
//           a_src = tanh(h)·w_src, a_dst = tanh(h)·w_dst.
// Block computes a 128x96 tile (one head), BK=16. 256 threads,
// each thread owns an 8x6 register tile (48 FMA per k-step, 14 LDS).
// ---------------------------------------------------------------------------
__global__ __launch_bounds__(256) void k_proj(
    const float* __restrict__ A,     // feat_in [8192, 768]
    const float* __restrict__ W,     // [H, 768, 96]
    const float* __restrict__ wsrc,  // [H, 96]
    const float* __restrict__ wdst)  // [H, 96]
{
    __shared__ float As[16][129];
    __shared__ float Ws[16][97];
    const int h    = blockIdx.y;
    const int row0 = blockIdx.x * 128;
    const int tid  = threadIdx.x;
    const int tx   = tid & 15, ty = tid >> 4;

    float acc[8][6];
#pragma unroll
    for (int r = 0; r < 8; ++r)
#pragma unroll
        for (int c = 0; c < 6; ++c) acc[r][c] = 0.f;

    const float* Wh = W + (size_t)h * 768 * 96;

    for (int k0 = 0; k0 < 768; k0 += 16) {
        // A tile: 128 rows x 16 k  (coalesced: 16 consecutive k per row)
#pragma unroll
        for (int idx = tid; idx < 2048; idx += 256) {
            int r = idx >> 4, kk = idx & 15;
            As[kk][r] = A[(size_t)(row0 + r) * 768 + (k0 + kk)];
        }
        // W tile: 16 k x 96 o (coalesced over o)
#pragma unroll
        for (int idx = tid; idx < 1536; idx += 256) {
            int kk = idx / 96, o = idx - kk * 96;
            Ws[kk][o] = Wh[(size_t)(k0 + kk) * 96 + o];
        }
        __syncthreads();
#pragma unroll
        for (int kk = 0; kk < 16; ++kk) {
            float a[8], w[6];
#pragma unroll
            for (int r = 0; r < 8; ++r) a[r] = As[kk][ty * 8 + r];
#pragma unroll
            for (int c = 0; c < 6; ++c) w[c] = Ws[kk][tx * 6 + c];
#pragma unroll
            for (int r = 0; r < 8; ++r)
#pragma unroll
                for (int c = 0; c < 6; ++c)
                    acc[r][c] = fmaf(a[r], w[c], acc[r][c]);
        }
        __syncthreads();
    }

    // Epilogue: store h, compute a_src/a_dst (reduce 96-dot across 16 tx lanes)
    float ws[6], wd[6];
#pragma unroll
    for (int c = 0; c < 6; ++c) {
        ws[c] = wsrc[h * 96 + tx * 6 + c];
        wd[c] = wdst[h * 96 + tx * 6 + c];
    }
    const int bh = (row0 >> 10) * 8 + h;   // 128 | 1024, so block has a single b
#pragma unroll
    for (int r = 0; r < 8; ++r) {
        int n = (row0 & 1023) + ty * 8 + r;
        float* hp = g_h + ((size_t)bh * 1024 + n) * 96;
        float ps = 0.f, pd = 0.f;
#pragma unroll
        for (int c = 0; c < 6; ++c) {
            float v = acc[r][c];
            hp[tx * 6 + c] = v;
            float t = tanhf(v);
            ps = fmaf(t, ws[c], ps);
            pd = fmaf(t, wd[c], pd);
        }
#pragma unroll
        for (int off = 8; off >= 1; off >>= 1) {   // tx groups are 16-lane aligned
            ps += __shfl_xor_sync(0xffffffffu, ps, off);
            pd += __shfl_xor_sync(0xffffffffu, pd, off);
        }
        if (tx == 0) {
            g_asrc[(size_t)bh * 1024 + n] = ps;
            g_adst[(size_t)bh * 1024 + n] = pd;
        }
    }
}

// ---------------------------------------------------------------------------
// Kernel 2: fused masked-softmax attention + aggregation + bias + elu.
// Block: one (b,h), 64 rows i. Logits recomputed on the fly (rank-1 + mask),
// softmax max in pass 1, unnormalized exp + P·h GEMM per 64-j chunk,
// normalize by accumulated sum at the end. 45 KB static SMEM.
// ---------------------------------------------------------------------------
__global__ __launch_bounds__(256) void k_attn(
    const float* __restrict__ adj,   // [B, 1024, 1024]
    const float* __restrict__ bias,  // [96]
    float* __restrict__ out)         // [B, 1024, 768]
{
    __shared__ float adsts[1024];
    __shared__ float asrcs[64];
    __shared__ float m_s[64];
    __shared__ float s_s[64];
    __shared__ float p_s[64][65];      // padded vs STS conflicts
    __shared__ float h_s[64 * 96];     // contiguous for float4 fill

    const int bh    = blockIdx.x;
    const int batch = bh >> 3, h = bh & 7;
    const int i0    = blockIdx.y * 64;
    const int tid   = threadIdx.x;

    for (int j = tid; j < 1024; j += 256)
        adsts[j] = g_adst[(size_t)bh * 1024 + j];
    if (tid < 64) asrcs[tid] = g_asrc[(size_t)bh * 1024 + i0 + tid];
    __syncthreads();

    const int r    = tid >> 2;     // row 0..63 (4 threads per row)
    const int slot = tid & 3;
    const float* adjrow = adj + ((size_t)batch * 1024 + i0 + r) * 1024;
    const float asr = asrcs[r];

    // Pass 1: row max of masked leaky-relu logits (adj read as float4)
    float m = -1e30f;
    for (int k = 0; k < 64; ++k) {
        int j = k * 16 + slot * 4;
        float4 av = *(const float4*)(adjrow + j);
        float ap[4] = {av.x, av.y, av.z, av.w};
#pragma unroll
        for (int t = 0; t < 4; ++t) {
            float l = asr + adsts[j + t];
            l = l >= 0.f ? l : LEAKY * l;
            l = (ap[t] == 0.f) ? -999.f : l;
            m = fmaxf(m, l);
        }
    }
    m = fmaxf(m, __shfl_xor_sync(0xffffffffu, m, 1));
    m = fmaxf(m, __shfl_xor_sync(0xffffffffu, m, 2));
    if (slot == 0) m_s[r] = m;
    __syncthreads();

    const float mi = m_s[r];
    const int tx = tid & 15, ty = tid >> 4;   // GEMM mapping: 4 rows x 6 cols
    float acc[4][6];
#pragma unroll
    for (int a = 0; a < 4; ++a)
#pragma unroll
        for (int c = 0; c < 6; ++c) acc[a][c] = 0.f;
    float ssum = 0.f;

    for (int c0 = 0; c0 < 1024; c0 += 64) {
        // p chunk: unnormalized exp(l - m_i), accumulate local sum
#pragma unroll
        for (int k = 0; k < 4; ++k) {
            int jj = k * 16 + slot * 4;
            float4 av = *(const float4*)(adjrow + c0 + jj);
            float ap[4] = {av.x, av.y, av.z, av.w};
#pragma unroll
            for (int t = 0; t < 4; ++t) {
                float l = asr + adsts[c0 + jj + t];
                l = l >= 0.f ? l : LEAKY * l;
                l = (ap[t] == 0.f) ? -999.f : l;
                float p = __expf(l - mi);
                p_s[r][jj + t] = p;
                ssum += p;
            }
        }
        // h chunk [64 x 96] via float4
        {
            const float4* src = (const float4*)(g_h + ((size_t)bh * 1024 + c0) * 96);
            float4* dst = (float4*)h_s;
#pragma unroll
            for (int idx = tid; idx < 64 * 96 / 4; idx += 256)
                dst[idx] = src[idx];
        }
        __syncthreads();
        // P·h accumulate: 24 FMA / 10 LDS per j (p broadcast, h conflict-free)
#pragma unroll 4
        for (int j = 0; j < 64; ++j) {
            float pv[4], hv[6];
#pragma unroll
            for (int a = 0; a < 4; ++a) pv[a] = p_s[ty * 4 + a][j];
#pragma unroll
            for (int c = 0; c < 6; ++c) hv[c] = h_s[j * 96 + tx * 6 + c];
#pragma unroll
            for (int a = 0; a < 4; ++a)
#pragma unroll
                for (int c = 0; c < 6; ++c)
                    acc[a][c] = fmaf(pv[a], hv[c], acc[a][c]);
        }
        __syncthreads();
    }

    ssum += __shfl_xor_sync(0xffffffffu, ssum, 1);
    ssum += __shfl_xor_sync(0xffffffffu, ssum, 2);
    if (slot == 0) s_s[r] = ssum;
    __syncthreads();

    // Normalize, + bias, elu, scatter to interleaved [b,n,h*96+o] layout
#pragma unroll
    for (int a = 0; a < 4; ++a) {
        int i = ty * 4 + a;
        float inv = 1.f / s_s[i];
        size_t ob = ((size_t)batch * 1024 + i0 + i) * 768 + h * 96;
#pragma unroll
        for (int c = 0; c < 6; ++c) {
            int o = tx * 6 + c;
            float v = fmaf(acc[a][c], inv, bias[o]);
            v = v > 0.f ? v : expm1f(v);
            out[ob + o] = v;
        }
    }
}

// ---------------------------------------------------------------------------
// Kernel 3: gate GEMM (feat_in @ Hw^T + Hb), sigmoid, final blend in-place:
//           out = g*feat_out + (1-g)*feat_in, feat_out read from d_out.
// Same 128x96 tiling as k_proj.
// ---------------------------------------------------------------------------
__global__ __launch_bounds__(256) void k_gate(
    const float* __restrict__ X,    // feat_in [8192, 768]
    const float* __restrict__ Hw,   // [768, 768]
    const float* __restrict__ Hb,   // [768]
    float* __restrict__ out)        // [8192, 768] (holds elu(feat_out))
{
    __shared__ float As[16][129];
    __shared__ float Ws[16][97];
    const int c0   = blockIdx.y * 96;
    const int row0 = blockIdx.x * 128;
    const int tid  = threadIdx.x;
    const int tx   = tid & 15, ty = tid >> 4;

    float acc[8][6];
#pragma unroll
    for (int r = 0; r < 8; ++r)
#pragma unroll
        for (int c = 0; c < 6; ++c) acc[r][c] = 0.f;

    for (int k0 = 0; k0 < 768; k0 += 16) {
#pragma unroll
        for (int idx = tid; idx < 2048; idx += 256) {
            int r = idx >> 4, kk = idx & 15;
            As[kk][r] = X[(size_t)(row0 + r) * 768 + (k0 + kk)];
        }
        // Hw row-major over i: thread reads 16 consecutive k per output col o
#pragma unroll
        for (int idx = tid; idx < 1536; idx += 256) {
            int o = idx >> 4, kk = idx & 15;
            Ws[kk][o] = Hw[(size_t)(c0 + o) * 768 + (k0 + kk)];
        }
        __syncthreads();
#pragma unroll
        for (int kk = 0; kk < 16; ++kk) {
            float a[8], w[6];
#pragma unroll
            for (int r = 0; r < 8; ++r) a[r] = As[kk][ty * 8 + r];
#pragma unroll
            for (int c = 0; c < 6; ++c) w[c] = Ws[kk][tx * 6 + c];
#pragma unroll
            for (int r = 0; r < 8; ++r)
#pragma unroll
                for (int c = 0; c < 6; ++c)
                    acc[r][c] = fmaf(a[r], w[c], acc[r][c]);
        }
        __syncthreads();
    }

#pragma unroll
    for (int r = 0; r < 8; ++r) {
        int row = row0 + ty * 8 + r;
#pragma unroll
        for (int c = 0; c < 6; ++c) {
            int col = c0 + tx * 6 + c;
            float g = 1.f / (1.f + __expf(-(acc[r][c] + Hb[col])));
            size_t idx = (size_t)row * 768 + col;
            float fo = out[idx];
            float xi = X[idx];
            out[idx] = fmaf(g, fo - xi, xi);   // g*fo + (1-g)*x
        }
    }
}

// ---------------------------------------------------------------------------
// Inputs (metadata order): feat_in, adj, W, b, w_src, w_dst, Hw, Hb
// ---------------------------------------------------------------------------
extern "C" void kernel_launch(void* const* d_in, const int* in_sizes, int n_in,
                              void* d_out, int out_size)
{
    const float* feat_in = (const float*)d_in[0];
    const float* adj     = (const float*)d_in[1];
    const float* W       = (const float*)d_in[2];
    const float* bias    = (const float*)d_in[3];
    const float* wsrc    = (const float*)d_in[4];
    const float* wdst    = (const float*)d_in[5];
    const float* Hw      = (const float*)d_in[6];
    const float* Hb      = (const float*)d_in[7];
    float* out           = (float*)d_out;
    (void)in_sizes; (void)n_in; (void)out_size;

    k_proj<<<dim3(64, 8), 256>>>(feat_in, W, wsrc, wdst);
    k_attn<<<dim3(64, 16), 256>>>(adj, bias, out);
    k_gate<<<dim3(64, 8), 256>>>(feat_in, Hw, Hb, out);
}

// round 7
// speedup vs baseline: 1.0214x; 1.0214x over previous
#include <cuda_runtime.h>
#include <math.h>

#define LEAKY 0.2f

// Scratch (allocation-free rule: __device__ globals)
__device__ float g_h[(size_t)8 * 8 * 1024 * 96];   // [b,h,n,o] fp32, 25.2 MB
__device__ float g_asrc[8 * 8 * 1024];             // [b,h,n]
__device__ float g_adst[8 * 8 * 1024];             // [b,h,n]

// ---------------------------------------------------------------------------
// Packed fp32x2 helpers (FFMA2 path — ptxas will not auto-fuse; must be PTX)
// ---------------------------------------------------------------------------
typedef unsigned long long u64;

__device__ __forceinline__ void fma2(u64& d, u64 a, u64 b) {
    asm("fma.rn.f32x2 %0, %1, %2, %0;" : "+l"(d) : "l"(a), "l"(b));
}
__device__ __forceinline__ u64 pack2(float lo, float hi) {
    u64 r; asm("mov.b64 %0, {%1, %2};" : "=l"(r) : "f"(lo), "f"(hi)); return r;
}
__device__ __forceinline__ void unpack2(u64 v, float& lo, float& hi) {
    asm("mov.b64 {%0, %1}, %2;" : "=f"(lo), "=f"(hi) : "l"(v));
}

// ---------------------------------------------------------------------------
// Kernel 1: per-head projection GEMM h = feat_in @ W[h], plus
//           a_src = tanh(h)·w_src, a_dst = tanh(h)·w_dst.
// 128x96 tile per block (one head), BK=16, 256 threads.
// f32x2: acc packed along rows (A pairs via LDS.64), W duplicated (w,w)
// with column map o = c*16+tx (stride-1 LDS.64 => conflict-free).
// ---------------------------------------------------------------------------
__global__ __launch_bounds__(256) void k_proj(
    const float* __restrict__ A,     // feat_in [8192, 768]
    const float* __restrict__ W,     // [H, 768, 96]
    const float* __restrict__ wsrc,  // [H, 96]
    const float* __restrict__ wdst)  // [H, 96]
{
    __shared__ __align__(16) float As[16][130];   // stride 130 => rows 8B-aligned
    __shared__ __align__(16) u64   Ws2[16][97];   // duplicated (w,w)
    const int h    = blockIdx.y;
    const int row0 = blockIdx.x * 128;
    const int tid  = threadIdx.x;
    const int tx   = tid & 15, ty = tid >> 4;

    u64 acc[4][6];
#pragma unroll
    for (int q = 0; q < 4; ++q)
#pragma unroll
        for (int c = 0; c < 6; ++c) acc[q][c] = 0ull;

    const float* Wh = W + (size_t)h * 768 * 96;

    for (int k0 = 0; k0 < 768; k0 += 16) {
        // A tile: 128 rows x 16 k  (coalesced: 16 consecutive k per row)
#pragma unroll
        for (int idx = tid; idx < 2048; idx += 256) {
            int r = idx >> 4, kk = idx & 15;
            As[kk][r] = A[(size_t)(row0 + r) * 768 + (k0 + kk)];
        }
        // W tile, duplicated: Ws2[kk][o] = (w,w)
#pragma unroll
        for (int idx = tid; idx < 1536; idx += 256) {
            int kk = idx / 96, o = idx - kk * 96;
            float w = Wh[(size_t)(k0 + kk) * 96 + o];
            Ws2[kk][o] = pack2(w, w);
        }
        __syncthreads();
#pragma unroll
        for (int kk = 0; kk < 16; ++kk) {
            u64 a01[4], wv[6];
#pragma unroll
            for (int q = 0; q < 4; ++q)
                a01[q] = *(const u64*)&As[kk][ty * 8 + 2 * q];
#pragma unroll
            for (int c = 0; c < 6; ++c)
                wv[c] = Ws2[kk][c * 16 + tx];
#pragma unroll
            for (int q = 0; q < 4; ++q)
#pragma unroll
                for (int c = 0; c < 6; ++c)
                    fma2(acc[q][c], a01[q], wv[c]);
        }
        __syncthreads();
    }

    // Epilogue: store h, compute a_src/a_dst (reduce 96-dot across 16 tx lanes)
    float ws[6], wd[6];
#pragma unroll
    for (int c = 0; c < 6; ++c) {
        int col = c * 16 + tx;
        ws[c] = wsrc[h * 96 + col];
        wd[c] = wdst[h * 96 + col];
    }
    const int bh = (row0 >> 10) * 8 + h;   // 128 | 1024, block has a single b
#pragma unroll
    for (int q = 0; q < 4; ++q) {
        float v0[6], v1[6];
#pragma unroll
        for (int c = 0; c < 6; ++c) unpack2(acc[q][c], v0[c], v1[c]);
#pragma unroll
        for (int s = 0; s < 2; ++s) {
            int n = (row0 & 1023) + ty * 8 + 2 * q + s;
            float* hp = g_h + ((size_t)bh * 1024 + n) * 96;
            float ps = 0.f, pd = 0.f;
#pragma unroll
            for (int c = 0; c < 6; ++c) {
                float v = s == 0 ? v0[c] : v1[c];
                hp[c * 16 + tx] = v;
                float t = tanhf(v);
                ps = fmaf(t, ws[c], ps);
                pd = fmaf(t, wd[c], pd);
            }
#pragma unroll
            for (int off = 8; off >= 1; off >>= 1) {  // 16-lane aligned groups
                ps += __shfl_xor_sync(0xffffffffu, ps, off);
                pd += __shfl_xor_sync(0xffffffffu, pd, off);
            }
            if (tx == 0) {
                g_asrc[(size_t)bh * 1024 + n] = ps;
                g_adst[(size_t)bh * 1024 + n] = pd;
            }
        }
    }
}

// ---------------------------------------------------------------------------
// Kernel 2: fused masked-softmax attention + aggregation + bias + elu.
// Block: one (b,h), 64 rows i. Logits recomputed on the fly (rank-1 + mask).
// P·h GEMM on f32x2: acc packed along O (h pairs natural LDS.64,
// conflict-free at stride 6 floats), p broadcast via mov.b64 pack (ALU pipe).
// ---------------------------------------------------------------------------
__global__ __launch_bounds__(256) void k_attn(
    const float* __restrict__ adj,   // [B, 1024, 1024]
    const float* __restrict__ bias,  // [96]
    float* __restrict__ out)         // [B, 1024, 768]
{
    __shared__ __align__(16) float adsts[1024];
    __shared__ float asrcs[64];
    __shared__ float m_s[64];
    __shared__ float s_s[64];
    __shared__ __align__(16) float p_s[64][65];
    __shared__ __align__(16) float h_s[64 * 96];

    const int bh    = blockIdx.x;
    const int batch = bh >> 3, h = bh & 7;
    const int i0    = blockIdx.y * 64;
    const int tid   = threadIdx.x;

    for (int j = tid; j < 1024; j += 256)
        adsts[j] = g_adst[(size_t)bh * 1024 + j];
    if (tid < 64) asrcs[tid] = g_asrc[(size_t)bh * 1024 + i0 + tid];
    __syncthreads();

    const int r    = tid >> 2;     // row 0..63 (4 threads per row)
    const int slot = tid & 3;
    const float* adjrow = adj + ((size_t)batch * 1024 + i0 + r) * 1024;
    const float asr = asrcs[r];

    // Pass 1: row max of masked leaky-relu logits (adj read as float4)
    float m = -1e30f;
    for (int k = 0; k < 64; ++k) {
        int j = k * 16 + slot * 4;
        float4 av = *(const float4*)(adjrow + j);
        float ap[4] = {av.x, av.y, av.z, av.w};
#pragma unroll
        for (int t = 0; t < 4; ++t) {
            float l = asr + adsts[j + t];
            l = l >= 0.f ? l : LEAKY * l;
            l = (ap[t] == 0.f) ? -999.f : l;
            m = fmaxf(m, l);
        }
    }
    m = fmaxf(m, __shfl_xor_sync(0xffffffffu, m, 1));
    m = fmaxf(m, __shfl_xor_sync(0xffffffffu, m, 2));
    if (slot == 0) m_s[r] = m;
    __syncthreads();

    const float mi = m_s[r];
    const int tx = tid & 15, ty = tid >> 4;   // GEMM mapping: 4 rows x 6 cols
    u64 acc[4][3];
#pragma unroll
    for (int a = 0; a < 4; ++a)
#pragma unroll
        for (int q = 0; q < 3; ++q) acc[a][q] = 0ull;
    float ssum = 0.f;

    for (int c0 = 0; c0 < 1024; c0 += 64) {
        // p chunk: unnormalized exp(l - m_i), accumulate local sum
#pragma unroll
        for (int k = 0; k < 4; ++k) {
            int jj = k * 16 + slot * 4;
            float4 av = *(const float4*)(adjrow + c0 + jj);
            float ap[4] = {av.x, av.y, av.z, av.w};
#pragma unroll
            for (int t = 0; t < 4; ++t) {
                float l = asr + adsts[c0 + jj + t];
                l = l >= 0.f ? l : LEAKY * l;
                l = (ap[t] == 0.f) ? -999.f : l;
                float p = __expf(l - mi);
                p_s[r][jj + t] = p;
                ssum += p;
            }
        }
        // h chunk [64 x 96] via float4
        {
            const float4* src = (const float4*)(g_h + ((size_t)bh * 1024 + c0) * 96);
            float4* dst = (float4*)h_s;
#pragma unroll
            for (int idx = tid; idx < 64 * 96 / 4; idx += 256)
                dst[idx] = src[idx];
        }
        __syncthreads();
        // P·h accumulate: 12 FFMA2 + 4 pack + 7 LDS per j for 24 FMAs
#pragma unroll 4
        for (int j = 0; j < 64; ++j) {
            u64 hv[3], pv[4];
#pragma unroll
            for (int q = 0; q < 3; ++q)
                hv[q] = *(const u64*)&h_s[j * 96 + tx * 6 + 2 * q];
#pragma unroll
            for (int a = 0; a < 4; ++a) {
                float p = p_s[ty * 4 + a][j];
                pv[a] = pack2(p, p);
            }
#pragma unroll
            for (int a = 0; a < 4; ++a)
#pragma unroll
                for (int q = 0; q < 3; ++q)
                    fma2(acc[a][q], pv[a], hv[q]);
        }
        __syncthreads();
    }

    ssum += __shfl_xor_sync(0xffffffffu, ssum, 1);
    ssum += __shfl_xor_sync(0xffffffffu, ssum, 2);
    if (slot == 0) s_s[r] = ssum;
    __syncthreads();

    // Normalize, + bias, elu, scatter to interleaved [b,n,h*96+o] layout
#pragma unroll
    for (int a = 0; a < 4; ++a) {
        int i = ty * 4 + a;
        float inv = 1.f / s_s[i];
        size_t ob = ((size_t)batch * 1024 + i0 + i) * 768 + h * 96;
#pragma unroll
        for (int q = 0; q < 3; ++q) {
            float v0, v1;
            unpack2(acc[a][q], v0, v1);
            int o0 = tx * 6 + 2 * q;
            float w0 = fmaf(v0, inv, bias[o0]);
            float w1 = fmaf(v1, inv, bias[o0 + 1]);
            w0 = w0 > 0.f ? w0 : expm1f(w0);
            w1 = w1 > 0.f ? w1 : expm1f(w1);
            out[ob + o0]     = w0;
            out[ob + o0 + 1] = w1;
        }
    }
}

// ---------------------------------------------------------------------------
// Kernel 3: gate GEMM (feat_in @ Hw^T + Hb), sigmoid, final blend in-place:
//           out = g*feat_out + (1-g)*feat_in, feat_out read from d_out.
// Same f32x2 tiling as k_proj.
// ---------------------------------------------------------------------------
__global__ __launch_bounds__(256) void k_gate(
    const float* __restrict__ X,    // feat_in [8192, 768]
    const float* __restrict__ Hw,   // [768, 768]
    const float* __restrict__ Hb,   // [768]
    float* __restrict__ out)        // [8192, 768] (holds elu(feat_out))
{
    __shared__ __align__(16) float As[16][130];
    __shared__ __align__(16) u64   Ws2[16][97];
    const int c0   = blockIdx.y * 96;
    const int row0 = blockIdx.x * 128;
    const int tid  = threadIdx.x;
    const int tx   = tid & 15, ty = tid >> 4;

    u64 acc[4][6];
#pragma unroll
    for (int q = 0; q < 4; ++q)
#pragma unroll
        for (int c = 0; c < 6; ++c) acc[q][c] = 0ull;

    for (int k0 = 0; k0 < 768; k0 += 16) {
#pragma unroll
        for (int idx = tid; idx < 2048; idx += 256) {
            int r = idx >> 4, kk = idx & 15;
            As[kk][r] = X[(size_t)(row0 + r) * 768 + (k0 + kk)];
        }
        // Hw row-major over i: 16 consecutive k per output col o; duplicated
#pragma unroll
        for (int idx = tid; idx < 1536; idx += 256) {
            int o = idx >> 4, kk = idx & 15;
            float w = Hw[(size_t)(c0 + o) * 768 + (k0 + kk)];
            Ws2[kk][o] = pack2(w, w);
        }
        __syncthreads();
#pragma unroll
        for (int kk = 0; kk < 16; ++kk) {
            u64 a01[4], wv[6];
#pragma unroll
            for (int q = 0; q < 4; ++q)
                a01[q] = *(const u64*)&As[kk][ty * 8 + 2 * q];
#pragma unroll
            for (int c = 0; c < 6; ++c)
                wv[c] = Ws2[kk][c * 16 + tx];
#pragma unroll
            for (int q = 0; q < 4; ++q)
#pragma unroll
                for (int c = 0; c < 6; ++c)
                    fma2(acc[q][c], a01[q], wv[c]);
        }
        __syncthreads();
    }

#pragma unroll
    for (int q = 0; q < 4; ++q) {
        float v0[6], v1[6];
#pragma unroll
        for (int c = 0; c < 6; ++c) unpack2(acc[q][c], v0[c], v1[c]);
#pragma unroll
        for (int s = 0; s < 2; ++s) {
            int row = row0 + ty * 8 + 2 * q + s;
#pragma unroll
            for (int c = 0; c < 6; ++c) {
                int col = c0 + c * 16 + tx;
                float v = s == 0 ? v0[c] : v1[c];
                float g = 1.f / (1.f + __expf(-(v + Hb[col])));
                size_t idx = (size_t)row * 768 + col;
                float fo = out[idx];
                float xi = X[idx];
                out[idx] = fmaf(g, fo - xi, xi);   // g*fo + (1-g)*x
            }
        }
    }
}

// ---------------------------------------------------------------------------
// Inputs (metadata order): feat_in, adj, W, b, w_src, w_dst, Hw, Hb
// ---------------------------------------------------------------------------
extern "C" void kernel_launch(void* const* d_in, const int* in_sizes, int n_in,
                              void* d_out, int out_size)
{
    const float* feat_in = (const float*)d_in[0];
    const float* adj     = (const float*)d_in[1];
    const float* W       = (const float*)d_in[2];
    const float* bias    = (const float*)d_in[3];
    const float* wsrc    = (const float*)d_in[4];
    const float* wdst    = (const float*)d_in[5];
    const float* Hw      = (const float*)d_in[6];
    const float* Hb      = (const float*)d_in[7];
    float* out           = (float*)d_out;
    (void)in_sizes; (void)n_in; (void)out_size;

    k_proj<<<dim3(64, 8), 256>>>(feat_in, W, wsrc, wdst);
    k_attn<<<dim3(64, 16), 256>>>(adj, bias, out);
    k_gate<<<dim3(64, 8), 256>>>(feat_in, Hw, Hb, out);
}

// round 9
// speedup vs baseline: 1.4266x; 1.3967x over previous
#include <cuda_runtime.h>
#include <cuda_bf16.h>
#include <math.h>
#include <stdint.h>

#define LEAKY 0.2f
typedef unsigned long long u64;

// ---------------------------------------------------------------------------
// Scratch (__device__ globals; no allocations allowed)
// ---------------------------------------------------------------------------
__device__ float g_h[(size_t)64 * 1024 * 96];      // [b*h][n][96] fp32
__device__ float g_asrc[64 * 1024];
__device__ float g_adst[64 * 1024];
__device__ __align__(16) __nv_bfloat16 g_Ah[8192 * 768];   // feat_in hi
__device__ __align__(16) __nv_bfloat16 g_Al[8192 * 768];   // feat_in lo
__device__ __align__(16) __nv_bfloat16 g_Wh[8 * 96 * 768]; // W^T per head [h][o][k], hi
__device__ __align__(16) __nv_bfloat16 g_Wl[8 * 96 * 768];
__device__ __align__(16) __nv_bfloat16 g_Hwh[768 * 768];   // Hw [o][k] (k-contig), hi
__device__ __align__(16) __nv_bfloat16 g_Hwl[768 * 768];

// ---------------------------------------------------------------------------
// fp32x2 helpers (k_attn keeps the proven R6 FFMA2 path)
// ---------------------------------------------------------------------------
__device__ __forceinline__ void fma2(u64& d, u64 a, u64 b) {
    asm("fma.rn.f32x2 %0, %1, %2, %0;" : "+l"(d) : "l"(a), "l"(b));
}
__device__ __forceinline__ u64 pack2(float lo, float hi) {
    u64 r; asm("mov.b64 %0, {%1, %2};" : "=l"(r) : "f"(lo), "f"(hi)); return r;
}
__device__ __forceinline__ void unpack2(u64 v, float& lo, float& hi) {
    asm("mov.b64 {%0, %1}, %2;" : "=f"(lo), "=f"(hi) : "l"(v));
}

// ---------------------------------------------------------------------------
// Warp-level bf16 MMA (sm_80+ PTX; lowers to HMMA on sm_103 — no 'a' feature)
// ---------------------------------------------------------------------------
__device__ __forceinline__ void mma16816(float* c, const uint32_t* a, const uint32_t* b) {
    asm volatile(
        "mma.sync.aligned.m16n8k16.row.col.f32.bf16.bf16.f32 "
        "{%0,%1,%2,%3}, {%4,%5,%6,%7}, {%8,%9}, {%0,%1,%2,%3};"
        : "+f"(c[0]), "+f"(c[1]), "+f"(c[2]), "+f"(c[3])
        : "r"(a[0]), "r"(a[1]), "r"(a[2]), "r"(a[3]), "r"(b[0]), "r"(b[1]));
}

// SMEM layout (dynamic). Operand tiles (rows padded to 80B, conflict-free for
// both uint4 fills and fragment LDS.32):
#define SM_AH  0            // 128 rows x 80B = 10240
#define SM_AL  10240        // 10240
#define SM_WH  20480        // 96 rows x 80B = 7680
#define SM_WL  28160        // 7680  (end 35840)
// Epilogue fp32 staging tile [128][97] overlaps operand region (used after):
#define SM_DT  0            // 49664 bytes
#define SM_VEC 49664        // 2 x 96 floats (or Hb slice)
#define SM_TOT 50432

// ---------------------------------------------------------------------------
// Prep: fp32 -> (bf16 hi, bf16 lo) splits
// ---------------------------------------------------------------------------
__global__ __launch_bounds__(256) void k_prep_a(
    const float* __restrict__ A, const float* __restrict__ Hw)
{
    int i = blockIdx.x * 256 + threadIdx.x;
    if (i < 8192 * 768) {
        float x = A[i];
        __nv_bfloat16 hi = __float2bfloat16(x);
        g_Ah[i] = hi;
        g_Al[i] = __float2bfloat16(x - __bfloat162float(hi));
    }
    if (i < 768 * 768) {
        float x = Hw[i];
        __nv_bfloat16 hi = __float2bfloat16(x);
        g_Hwh[i] = hi;
        g_Hwl[i] = __float2bfloat16(x - __bfloat162float(hi));
    }
}
__global__ __launch_bounds__(256) void k_prep_w(const float* __restrict__ W)
{
    int i = blockIdx.x * 256 + threadIdx.x;
    if (i < 8 * 96 * 768) {
        int k = i % 768, t = i / 768;
        int o = t % 96, hh = t / 96;
        float x = W[((size_t)hh * 768 + k) * 96 + o];
        __nv_bfloat16 hi = __float2bfloat16(x);
        g_Wh[i] = hi;
        g_Wl[i] = __float2bfloat16(x - __bfloat162float(hi));
    }
}

// ---------------------------------------------------------------------------
// Kernel 1 (HMMA): h = feat_in @ W[h]; epilogue computes a_src/a_dst.
// Block: 128x96 tile, 8 warps (4M x 2N), K in 24 chunks of 32.
// bf16 split: D = Ah*Wh + Ah*Wl + Al*Wh (fp32 accum).
// ---------------------------------------------------------------------------
__global__ __launch_bounds__(256) void k_proj_mma(
    const float* __restrict__ wsrc, const float* __restrict__ wdst)
{
    extern __shared__ __align__(16) char ds[];
    const int tid  = threadIdx.x;
    const int wid  = tid >> 5, lane = tid & 31;
    const int g    = lane >> 2, tig = lane & 3;
    const int wm   = wid & 3, wn = wid >> 2;
    const int row0 = blockIdx.x * 128, h = blockIdx.y;

    float* wsv = (float*)(ds + SM_VEC);
    if (tid < 96) {
        wsv[tid]      = wsrc[h * 96 + tid];
        wsv[96 + tid] = wdst[h * 96 + tid];
    }

    float acc[2][6][4];
#pragma unroll
    for (int ma = 0; ma < 2; ++ma)
#pragma unroll
        for (int na = 0; na < 6; ++na)
#pragma unroll
            for (int q = 0; q < 4; ++q) acc[ma][na][q] = 0.f;

    const uint4* __restrict__ Ah4 = (const uint4*)g_Ah;
    const uint4* __restrict__ Al4 = (const uint4*)g_Al;
    const uint4* __restrict__ Wh4 = (const uint4*)g_Wh;
    const uint4* __restrict__ Wl4 = (const uint4*)g_Wl;

    for (int ch = 0; ch < 24; ++ch) {
        // A tiles: 128 rows x 32 bf16 (4 uint4/row), hi+lo
#pragma unroll
        for (int it = 0; it < 2; ++it) {
            int idx = tid + it * 256;
            int r = idx >> 2, c = idx & 3;
            int src = (row0 + r) * 96 + ch * 4 + c;
            *(uint4*)(ds + SM_AH + r * 80 + c * 16) = Ah4[src];
            *(uint4*)(ds + SM_AL + r * 80 + c * 16) = Al4[src];
        }
        // W tiles: 96 rows (o) x 32 bf16 (k), hi+lo
#pragma unroll
        for (int it = 0; it < 2; ++it) {
            int idx = tid + it * 256;
            if (idx < 384) {
                int r = idx >> 2, c = idx & 3;
                int src = (h * 96 + r) * 96 + ch * 4 + c;
                *(uint4*)(ds + SM_WH + r * 80 + c * 16) = Wh4[src];
                *(uint4*)(ds + SM_WL + r * 80 + c * 16) = Wl4[src];
            }
        }
        __syncthreads();
#pragma unroll
        for (int ks = 0; ks < 2; ++ks) {
            const int kb = ks * 32;            // byte offset of k0 within row
            uint32_t ahi[2][4], alo[2][4];
#pragma unroll
            for (int ma = 0; ma < 2; ++ma) {
                int rb = wm * 32 + ma * 16;
                ahi[ma][0] = *(const uint32_t*)(ds + SM_AH + (rb + g)     * 80 + kb + tig * 4);
                ahi[ma][1] = *(const uint32_t*)(ds + SM_AH + (rb + g + 8) * 80 + kb + tig * 4);
                ahi[ma][2] = *(const uint32_t*)(ds + SM_AH + (rb + g)     * 80 + kb + 16 + tig * 4);
                ahi[ma][3] = *(const uint32_t*)(ds + SM_AH + (rb + g + 8) * 80 + kb + 16 + tig * 4);
                alo[ma][0] = *(const uint32_t*)(ds + SM_AL + (rb + g)     * 80 + kb + tig * 4);
                alo[ma][1] = *(const uint32_t*)(ds + SM_AL + (rb + g + 8) * 80 + kb + tig * 4);
                alo[ma][2] = *(const uint32_t*)(ds + SM_AL + (rb + g)     * 80 + kb + 16 + tig * 4);
                alo[ma][3] = *(const uint32_t*)(ds + SM_AL + (rb + g + 8) * 80 + kb + 16 + tig * 4);
            }
#pragma unroll
            for (int na = 0; na < 6; ++na) {
                int n = wn * 48 + na * 8 + g;
                uint32_t bhi[2], blo[2];
                bhi[0] = *(const uint32_t*)(ds + SM_WH + n * 80 + kb + tig * 4);
                bhi[1] = *(const uint32_t*)(ds + SM_WH + n * 80 + kb + 16 + tig * 4);
                blo[0] = *(const uint32_t*)(ds + SM_WL + n * 80 + kb + tig * 4);
                blo[1] = *(const uint32_t*)(ds + SM_WL + n * 80 + kb + 16 + tig * 4);
#pragma unroll
                for (int ma = 0; ma < 2; ++ma) {
                    mma16816(acc[ma][na], ahi[ma], bhi);
                    mma16816(acc[ma][na], ahi[ma], blo);
                    mma16816(acc[ma][na], alo[ma], bhi);
                }
            }
        }
        __syncthreads();
    }

    // Stage C into fp32 tile [128][97]
    float* dtile = (float*)(ds + SM_DT);
#pragma unroll
    for (int ma = 0; ma < 2; ++ma)
#pragma unroll
        for (int na = 0; na < 6; ++na) {
            int rb = wm * 32 + ma * 16 + g;
            int cb = wn * 48 + na * 8 + 2 * tig;
            dtile[rb * 97 + cb]           = acc[ma][na][0];
            dtile[rb * 97 + cb + 1]       = acc[ma][na][1];
            dtile[(rb + 8) * 97 + cb]     = acc[ma][na][2];
            dtile[(rb + 8) * 97 + cb + 1] = acc[ma][na][3];
        }
    __syncthreads();

    const int batch = row0 >> 10, bh = batch * 8 + h;
    {   // a_src/a_dst: 2 threads per row
        int r = tid >> 1, half = tid & 1;
        float ps = 0.f, pd = 0.f;
#pragma unroll
        for (int cc = 0; cc < 48; ++cc) {
            int c = half * 48 + cc;
            float t = tanhf(dtile[r * 97 + c]);
            ps = fmaf(t, wsv[c], ps);
            pd = fmaf(t, wsv[96 + c], pd);
        }
        ps += __shfl_xor_sync(0xffffffffu, ps, 1);
        pd += __shfl_xor_sync(0xffffffffu, pd, 1);
        if (half == 0) {
            g_asrc[(size_t)bh * 1024 + (row0 & 1023) + r] = ps;
            g_adst[(size_t)bh * 1024 + (row0 & 1023) + r] = pd;
        }
    }
    float* hout = g_h + ((size_t)bh * 1024 + (row0 & 1023)) * 96;
    for (int i = tid; i < 128 * 96; i += 256) {
        int r = i / 96, c = i - r * 96;
        hout[i] = dtile[r * 97 + c];
    }
}

// ---------------------------------------------------------------------------
// Kernel 3 (HMMA): gate GEMM feat_in @ Hw^T + Hb -> sigmoid -> blend in-place.
// ---------------------------------------------------------------------------
__global__ __launch_bounds__(256) void k_gate_mma(
    const float* __restrict__ X, const float* __restrict__ Hb,
    float* __restrict__ out)
{
    extern __shared__ __align__(16) char ds[];
    const int tid  = threadIdx.x;
    const int wid  = tid >> 5, lane = tid & 31;
    const int g    = lane >> 2, tig = lane & 3;
    const int wm   = wid & 3, wn = wid >> 2;
    const int row0 = blockIdx.x * 128, c0 = blockIdx.y * 96;

    float* hbv = (float*)(ds + SM_VEC);
    if (tid < 96) hbv[tid] = Hb[c0 + tid];

    float acc[2][6][4];
#pragma unroll
    for (int ma = 0; ma < 2; ++ma)
#pragma unroll
        for (int na = 0; na < 6; ++na)
#pragma unroll
            for (int q = 0; q < 4; ++q) acc[ma][na][q] = 0.f;

    const uint4* __restrict__ Ah4 = (const uint4*)g_Ah;
    const uint4* __restrict__ Al4 = (const uint4*)g_Al;
    const uint4* __restrict__ Wh4 = (const uint4*)g_Hwh;
    const uint4* __restrict__ Wl4 = (const uint4*)g_Hwl;

    for (int ch = 0; ch < 24; ++ch) {
#pragma unroll
        for (int it = 0; it < 2; ++it) {
            int idx = tid + it * 256;
            int r = idx >> 2, c = idx & 3;
            int src = (row0 + r) * 96 + ch * 4 + c;
            *(uint4*)(ds + SM_AH + r * 80 + c * 16) = Ah4[src];
            *(uint4*)(ds + SM_AL + r * 80 + c * 16) = Al4[src];
        }
#pragma unroll
        for (int it = 0; it < 2; ++it) {
            int idx = tid + it * 256;
            if (idx < 384) {
                int r = idx >> 2, c = idx & 3;
                int src = (c0 + r) * 96 + ch * 4 + c;
                *(uint4*)(ds + SM_WH + r * 80 + c * 16) = Wh4[src];
                *(uint4*)(ds + SM_WL + r * 80 + c * 16) = Wl4[src];
            }
        }
        __syncthreads();
#pragma unroll
        for (int ks = 0; ks < 2; ++ks) {
            const int kb = ks * 32;
            uint32_t ahi[2][4], alo[2][4];
#pragma unroll
            for (int ma = 0; ma < 2; ++ma) {
                int rb = wm * 32 + ma * 16;
                ahi[ma][0] = *(const uint32_t*)(ds + SM_AH + (rb + g)     * 80 + kb + tig * 4);
                ahi[ma][1] = *(const uint32_t*)(ds + SM_AH + (rb + g + 8) * 80 + kb + tig * 4);
                ahi[ma][2] = *(const uint32_t*)(ds + SM_AH + (rb + g)     * 80 + kb + 16 + tig * 4);
                ahi[ma][3] = *(const uint32_t*)(ds + SM_AH + (rb + g + 8) * 80 + kb + 16 + tig * 4);
                alo[ma][0] = *(const uint32_t*)(ds + SM_AL + (rb + g)     * 80 + kb + tig * 4);
                alo[ma][1] = *(const uint32_t*)(ds + SM_AL + (rb + g + 8) * 80 + kb + tig * 4);
                alo[ma][2] = *(const uint32_t*)(ds + SM_AL + (rb + g)     * 80 + kb + 16 + tig * 4);
                alo[ma][3] = *(const uint32_t*)(ds + SM_AL + (rb + g + 8) * 80 + kb + 16 + tig * 4);
            }
#pragma unroll
            for (int na = 0; na < 6; ++na) {
                int n = wn * 48 + na * 8 + g;
                uint32_t bhi[2], blo[2];
                bhi[0] = *(const uint32_t*)(ds + SM_WH + n * 80 + kb + tig * 4);
                bhi[1] = *(const uint32_t*)(ds + SM_WH + n * 80 + kb + 16 + tig * 4);
                blo[0] = *(const uint32_t*)(ds + SM_WL + n * 80 + kb + tig * 4);
                blo[1] = *(const uint32_t*)(ds + SM_WL + n * 80 + kb + 16 + tig * 4);
#pragma unroll
                for (int ma = 0; ma < 2; ++ma) {
                    mma16816(acc[ma][na], ahi[ma], bhi);
                    mma16816(acc[ma][na], ahi[ma], blo);
                    mma16816(acc[ma][na], alo[ma], bhi);
                }
            }
        }
        __syncthreads();
    }

    float* dtile = (float*)(ds + SM_DT);
#pragma unroll
    for (int ma = 0; ma < 2; ++ma)
#pragma unroll
        for (int na = 0; na < 6; ++na) {
            int rb = wm * 32 + ma * 16 + g;
            int cb = wn * 48 + na * 8 + 2 * tig;
            dtile[rb * 97 + cb]           = acc[ma][na][0];
            dtile[rb * 97 + cb + 1]       = acc[ma][na][1];
            dtile[(rb + 8) * 97 + cb]     = acc[ma][na][2];
            dtile[(rb + 8) * 97 + cb + 1] = acc[ma][na][3];
        }
    __syncthreads();

    for (int i = tid; i < 128 * 96; i += 256) {
        int r = i / 96, c = i - r * 96;
        int row = row0 + r, col = c0 + c;
        float v = dtile[r * 97 + c];
        float gg = 1.f / (1.f + __expf(-(v + hbv[c])));
        size_t idx = (size_t)row * 768 + col;
        float fo = out[idx], xi = X[idx];
        out[idx] = fmaf(gg, fo - xi, xi);
    }
}

// ---------------------------------------------------------------------------
// Kernel 2: fused masked-softmax attention (UNCHANGED — proven R6 version)
// ---------------------------------------------------------------------------
__global__ __launch_bounds__(256) void k_attn(
    const float* __restrict__ adj,   // [B, 1024, 1024]
    const float* __restrict__ bias,  // [96]
    float* __restrict__ out)         // [B, 1024, 768]
{
    __shared__ __align__(16) float adsts[1024];
    __shared__ float asrcs[64];
    __shared__ float m_s[64];
    __shared__ float s_s[64];
    __shared__ __align__(16) float p_s[64][65];
    __shared__ __align__(16) float h_s[64 * 96];

    const int bh    = blockIdx.x;
    const int batch = bh >> 3;
    const int i0    = blockIdx.y * 64;
    const int tid   = threadIdx.x;

    for (int j = tid; j < 1024; j += 256)
        adsts[j] = g_adst[(size_t)bh * 1024 + j];
    if (tid < 64) asrcs[tid] = g_asrc[(size_t)bh * 1024 + i0 + tid];
    __syncthreads();

    const int r    = tid >> 2;
    const int slot = tid & 3;
    const float* adjrow = adj + ((size_t)batch * 1024 + i0 + r) * 1024;
    const float asr = asrcs[r];

    float m = -1e30f;
    for (int k = 0; k < 64; ++k) {
        int j = k * 16 + slot * 4;
        float4 av = *(const float4*)(adjrow + j);
        float ap[4] = {av.x, av.y, av.z, av.w};
#pragma unroll
        for (int t = 0; t < 4; ++t) {
            float l = asr + adsts[j + t];
            l = l >= 0.f ? l : LEAKY * l;
            l = (ap[t] == 0.f) ? -999.f : l;
            m = fmaxf(m, l);
        }
    }
    m = fmaxf(m, __shfl_xor_sync(0xffffffffu, m, 1));
    m = fmaxf(m, __shfl_xor_sync(0xffffffffu, m, 2));
    if (slot == 0) m_s[r] = m;
    __syncthreads();

    const float mi = m_s[r];
    const int tx = tid & 15, ty = tid >> 4;
    u64 acc[4][3];
#pragma unroll
    for (int a = 0; a < 4; ++a)
#pragma unroll
        for (int q = 0; q < 3; ++q) acc[a][q] = 0ull;
    float ssum = 0.f;

    for (int c0 = 0; c0 < 1024; c0 += 64) {
#pragma unroll
        for (int k = 0; k < 4; ++k) {
            int jj = k * 16 + slot * 4;
            float4 av = *(const float4*)(adjrow + c0 + jj);
            float ap[4] = {av.x, av.y, av.z, av.w};
#pragma unroll
            for (int t = 0; t < 4; ++t) {
                float l = asr + adsts[c0 + jj + t];
                l = l >= 0.f ? l : LEAKY * l;
                l = (ap[t] == 0.f) ? -999.f : l;
                float p = __expf(l - mi);
                p_s[r][jj + t] = p;
                ssum += p;
            }
        }
        {
            const float4* src = (const float4*)(g_h + ((size_t)bh * 1024 + c0) * 96);
            float4* dst = (float4*)h_s;
#pragma unroll
            for (int idx = tid; idx < 64 * 96 / 4; idx += 256)
                dst[idx] = src[idx];
        }
        __syncthreads();
#pragma unroll 4
        for (int j = 0; j < 64; ++j) {
            u64 hv[3], pv[4];
#pragma unroll
            for (int q = 0; q < 3; ++q)
                hv[q] = *(const u64*)&h_s[j * 96 + tx * 6 + 2 * q];
#pragma unroll
            for (int a = 0; a < 4; ++a) {
                float p = p_s[ty * 4 + a][j];
                pv[a] = pack2(p, p);
            }
#pragma unroll
            for (int a = 0; a < 4; ++a)
#pragma unroll
                for (int q = 0; q < 3; ++q)
                    fma2(acc[a][q], pv[a], hv[q]);
        }
        __syncthreads();
    }

    ssum += __shfl_xor_sync(0xffffffffu, ssum, 1);
    ssum += __shfl_xor_sync(0xffffffffu, ssum, 2);
    if (slot == 0) s_s[r] = ssum;
    __syncthreads();

    const int h = bh & 7;
#pragma unroll
    for (int a = 0; a < 4; ++a) {
        int i = ty * 4 + a;
        float inv = 1.f / s_s[i];
        size_t ob = ((size_t)batch * 1024 + i0 + i) * 768 + h * 96;
#pragma unroll
        for (int q = 0; q < 3; ++q) {
            float v0, v1;
            unpack2(acc[a][q], v0, v1);
            int o0 = tx * 6 + 2 * q;
            float w0 = fmaf(v0, inv, bias[o0]);
            float w1 = fmaf(v1, inv, bias[o0 + 1]);
            w0 = w0 > 0.f ? w0 : expm1f(w0);
            w1 = w1 > 0.f ? w1 : expm1f(w1);
            out[ob + o0]     = w0;
            out[ob + o0 + 1] = w1;
        }
    }
}

// ---------------------------------------------------------------------------
// Inputs (metadata order): feat_in, adj, W, b, w_src, w_dst, Hw, Hb
// ---------------------------------------------------------------------------
extern "C" void kernel_launch(void* const* d_in, const int* in_sizes, int n_in,
                              void* d_out, int out_size)
{
    const float* feat_in = (const float*)d_in[0];
    const float* adj     = (const float*)d_in[1];
    const float* W       = (const float*)d_in[2];
    const float* bias    = (const float*)d_in[3];
    const float* wsrc    = (const float*)d_in[4];
    const float* wdst    = (const float*)d_in[5];
    const float* Hw      = (const float*)d_in[6];
    const float* Hb      = (const float*)d_in[7];
    float* out           = (float*)d_out;
    (void)in_sizes; (void)n_in; (void)out_size;

    static bool attr_done = false;
    if (!attr_done) {
        cudaFuncSetAttribute(k_proj_mma, cudaFuncAttributeMaxDynamicSharedMemorySize, SM_TOT);
        cudaFuncSetAttribute(k_gate_mma, cudaFuncAttributeMaxDynamicSharedMemorySize, SM_TOT);
        attr_done = true;
    }

    k_prep_a<<<(8192 * 768 + 255) / 256, 256>>>(feat_in, Hw);
    k_prep_w<<<(8 * 96 * 768 + 255) / 256, 256>>>(W);
    k_proj_mma<<<dim3(64, 8), 256, SM_TOT>>>(wsrc, wdst);
    k_attn<<<dim3(64, 16), 256>>>(adj, bias, out);
    k_gate_mma<<<dim3(64, 8), 256, SM_TOT>>>(feat_in, Hb, out);
}

// round 10
// speedup vs baseline: 1.8463x; 1.2942x over previous
#include <cuda_runtime.h>
#include <cuda_bf16.h>
#include <math.h>
#include <stdint.h>

#define LEAKY 0.2f
typedef unsigned long long u64;

// ---------------------------------------------------------------------------
// Scratch (__device__ globals; no allocations allowed)
// ---------------------------------------------------------------------------
__device__ float g_asrc[64 * 1024];
__device__ float g_adst[64 * 1024];
__device__ __align__(16) __nv_bfloat16 g_Ah[8192 * 768];    // feat_in hi
__device__ __align__(16) __nv_bfloat16 g_Al[8192 * 768];    // feat_in lo
__device__ __align__(16) __nv_bfloat16 g_Wh[8 * 96 * 768];  // W^T [h][o][k] hi
__device__ __align__(16) __nv_bfloat16 g_Wl[8 * 96 * 768];
__device__ __align__(16) __nv_bfloat16 g_Hwh[768 * 768];    // Hw [o][k] hi
__device__ __align__(16) __nv_bfloat16 g_Hwl[768 * 768];
__device__ __align__(16) __nv_bfloat16 g_hTh[(size_t)64 * 96 * 1024]; // h^T [bh][o][n] hi
__device__ __align__(16) __nv_bfloat16 g_hTl[(size_t)64 * 96 * 1024]; // lo

// ---------------------------------------------------------------------------
// Warp-level bf16 MMA (sm_80+ PTX; lowers to HMMA on sm_103)
// ---------------------------------------------------------------------------
__device__ __forceinline__ void mma16816(float* c, const uint32_t* a, const uint32_t* b) {
    asm volatile(
        "mma.sync.aligned.m16n8k16.row.col.f32.bf16.bf16.f32 "
        "{%0,%1,%2,%3}, {%4,%5,%6,%7}, {%8,%9}, {%0,%1,%2,%3};"
        : "+f"(c[0]), "+f"(c[1]), "+f"(c[2]), "+f"(c[3])
        : "r"(a[0]), "r"(a[1]), "r"(a[2]), "r"(a[3]), "r"(b[0]), "r"(b[1]));
}
__device__ __forceinline__ uint32_t pack_bf2(float a, float b) {
    __nv_bfloat162 t = __floats2bfloat162_rn(a, b);
    return *(uint32_t*)&t;
}

// SMEM layout (GEMM kernels): operand tiles, 80B row stride (conflict-free
// for uint4 fills and 32-bit fragment loads: bank = 4*(row&7) + word).
#define SM_AH  0            // 128 x 80B
#define SM_AL  10240
#define SM_WH  20480        // 96 x 80B
#define SM_WL  28160        // end 35840
#define SM_DT  0            // epilogue fp32 tile [128][97] overlays operands
#define SM_VEC 49664
#define SM_TOT 50432

// attn kernel layout
#define SM2_PH   0          // 128 x 80B
#define SM2_PL   10240
#define SM2_HH   20480      // 96 x 80B
#define SM2_HL   28160      // end 35840
#define SM2_ADST 35840      // 1024 f32
#define SM2_SS   49664      // 128 f32 (beyond dtile overlay)
#define SM2_TOT  50176

// ---------------------------------------------------------------------------
// Prep: fp32 -> (bf16 hi, bf16 lo) splits
// ---------------------------------------------------------------------------
__global__ __launch_bounds__(256) void k_prep_a(
    const float* __restrict__ A, const float* __restrict__ Hw)
{
    int i = blockIdx.x * 256 + threadIdx.x;
    if (i < 8192 * 768) {
        float x = A[i];
        __nv_bfloat16 hi = __float2bfloat16(x);
        g_Ah[i] = hi;
        g_Al[i] = __float2bfloat16(x - __bfloat162float(hi));
    }
    if (i < 768 * 768) {
        float x = Hw[i];
        __nv_bfloat16 hi = __float2bfloat16(x);
        g_Hwh[i] = hi;
        g_Hwl[i] = __float2bfloat16(x - __bfloat162float(hi));
    }
}
__global__ __launch_bounds__(256) void k_prep_w(const float* __restrict__ W)
{
    int i = blockIdx.x * 256 + threadIdx.x;
    if (i < 8 * 96 * 768) {
        int k = i % 768, t = i / 768;
        int o = t % 96, hh = t / 96;
        float x = W[((size_t)hh * 768 + k) * 96 + o];
        __nv_bfloat16 hi = __float2bfloat16(x);
        g_Wh[i] = hi;
        g_Wl[i] = __float2bfloat16(x - __bfloat162float(hi));
    }
}

// ---------------------------------------------------------------------------
// Kernel 1 (HMMA): h = feat_in @ W[h]; epilogue: a_src/a_dst + h^T bf16 split.
// ---------------------------------------------------------------------------
__global__ __launch_bounds__(256) void k_proj_mma(
    const float* __restrict__ wsrc, const float* __restrict__ wdst)
{
    extern __shared__ __align__(16) char ds[];
    const int tid  = threadIdx.x;
    const int wid  = tid >> 5, lane = tid & 31;
    const int g    = lane >> 2, tig = lane & 3;
    const int wm   = wid & 3, wn = wid >> 2;
    const int row0 = blockIdx.x * 128, h = blockIdx.y;

    float* wsv = (float*)(ds + SM_VEC);
    if (tid < 96) {
        wsv[tid]      = wsrc[h * 96 + tid];
        wsv[96 + tid] = wdst[h * 96 + tid];
    }

    float acc[2][6][4];
#pragma unroll
    for (int ma = 0; ma < 2; ++ma)
#pragma unroll
        for (int na = 0; na < 6; ++na)
#pragma unroll
            for (int q = 0; q < 4; ++q) acc[ma][na][q] = 0.f;

    const uint4* __restrict__ Ah4 = (const uint4*)g_Ah;
    const uint4* __restrict__ Al4 = (const uint4*)g_Al;
    const uint4* __restrict__ Wh4 = (const uint4*)g_Wh;
    const uint4* __restrict__ Wl4 = (const uint4*)g_Wl;

    for (int ch = 0; ch < 24; ++ch) {
#pragma unroll
        for (int it = 0; it < 2; ++it) {
            int idx = tid + it * 256;
            int r = idx >> 2, c = idx & 3;
            int src = (row0 + r) * 96 + ch * 4 + c;
            *(uint4*)(ds + SM_AH + r * 80 + c * 16) = Ah4[src];
            *(uint4*)(ds + SM_AL + r * 80 + c * 16) = Al4[src];
        }
#pragma unroll
        for (int it = 0; it < 2; ++it) {
            int idx = tid + it * 256;
            if (idx < 384) {
                int r = idx >> 2, c = idx & 3;
                int src = (h * 96 + r) * 96 + ch * 4 + c;
                *(uint4*)(ds + SM_WH + r * 80 + c * 16) = Wh4[src];
                *(uint4*)(ds + SM_WL + r * 80 + c * 16) = Wl4[src];
            }
        }
        __syncthreads();
#pragma unroll
        for (int ks = 0; ks < 2; ++ks) {
            const int kb = ks * 32;
            uint32_t ahi[2][4], alo[2][4];
#pragma unroll
            for (int ma = 0; ma < 2; ++ma) {
                int rb = wm * 32 + ma * 16;
                ahi[ma][0] = *(const uint32_t*)(ds + SM_AH + (rb + g)     * 80 + kb + tig * 4);
                ahi[ma][1] = *(const uint32_t*)(ds + SM_AH + (rb + g + 8) * 80 + kb + tig * 4);
                ahi[ma][2] = *(const uint32_t*)(ds + SM_AH + (rb + g)     * 80 + kb + 16 + tig * 4);
                ahi[ma][3] = *(const uint32_t*)(ds + SM_AH + (rb + g + 8) * 80 + kb + 16 + tig * 4);
                alo[ma][0] = *(const uint32_t*)(ds + SM_AL + (rb + g)     * 80 + kb + tig * 4);
                alo[ma][1] = *(const uint32_t*)(ds + SM_AL + (rb + g + 8) * 80 + kb + tig * 4);
                alo[ma][2] = *(const uint32_t*)(ds + SM_AL + (rb + g)     * 80 + kb + 16 + tig * 4);
                alo[ma][3] = *(const uint32_t*)(ds + SM_AL + (rb + g + 8) * 80 + kb + 16 + tig * 4);
            }
#pragma unroll
            for (int na = 0; na < 6; ++na) {
                int n = wn * 48 + na * 8 + g;
                uint32_t bhi[2], blo[2];
                bhi[0] = *(const uint32_t*)(ds + SM_WH + n * 80 + kb + tig * 4);
                bhi[1] = *(const uint32_t*)(ds + SM_WH + n * 80 + kb + 16 + tig * 4);
                blo[0] = *(const uint32_t*)(ds + SM_WL + n * 80 + kb + tig * 4);
                blo[1] = *(const uint32_t*)(ds + SM_WL + n * 80 + kb + 16 + tig * 4);
#pragma unroll
                for (int ma = 0; ma < 2; ++ma) {
                    mma16816(acc[ma][na], ahi[ma], bhi);
                    mma16816(acc[ma][na], ahi[ma], blo);
                    mma16816(acc[ma][na], alo[ma], bhi);
                }
            }
        }
        __syncthreads();
    }

    float* dtile = (float*)(ds + SM_DT);
#pragma unroll
    for (int ma = 0; ma < 2; ++ma)
#pragma unroll
        for (int na = 0; na < 6; ++na) {
            int rb = wm * 32 + ma * 16 + g;
            int cb = wn * 48 + na * 8 + 2 * tig;
            dtile[rb * 97 + cb]           = acc[ma][na][0];
            dtile[rb * 97 + cb + 1]       = acc[ma][na][1];
            dtile[(rb + 8) * 97 + cb]     = acc[ma][na][2];
            dtile[(rb + 8) * 97 + cb + 1] = acc[ma][na][3];
        }
    __syncthreads();

    const int batch = row0 >> 10, bh = batch * 8 + h;
    const int nbase = row0 & 1023;
    {   // a_src/a_dst: 2 threads per row
        int r = tid >> 1, half = tid & 1;
        float ps = 0.f, pd = 0.f;
#pragma unroll
        for (int cc = 0; cc < 48; ++cc) {
            int c = half * 48 + cc;
            float t = tanhf(dtile[r * 97 + c]);
            ps = fmaf(t, wsv[c], ps);
            pd = fmaf(t, wsv[96 + c], pd);
        }
        ps += __shfl_xor_sync(0xffffffffu, ps, 1);
        pd += __shfl_xor_sync(0xffffffffu, pd, 1);
        if (half == 0) {
            g_asrc[(size_t)bh * 1024 + nbase + r] = ps;
            g_adst[(size_t)bh * 1024 + nbase + r] = pd;
        }
    }
    // h^T bf16 split, coalesced along n (u32 = 2 bf16)
    for (int idx = tid; idx < 96 * 64; idx += 256) {
        int o = idx >> 6, nw = idx & 63;
        float v0 = dtile[(2 * nw) * 97 + o];
        float v1 = dtile[(2 * nw + 1) * 97 + o];
        __nv_bfloat16 b0 = __float2bfloat16(v0);
        __nv_bfloat16 b1 = __float2bfloat16(v1);
        uint32_t hi = pack_bf2(v0, v1);   // rn-pack of both
        uint32_t lo = pack_bf2(v0 - __bfloat162float(b0), v1 - __bfloat162float(b1));
        size_t dst = ((size_t)bh * 96 + o) * 512 + (nbase >> 1) + nw;
        ((uint32_t*)g_hTh)[dst] = hi;
        ((uint32_t*)g_hTl)[dst] = lo;
    }
}

// ---------------------------------------------------------------------------
// Kernel 2 (HMMA): fused masked-softmax attention, single pass (no row max:
// logits bounded by tanh'd dots, exp never overflows; exp(-999)=0 masks).
// D = P·h via 3-term bf16 split MMA; normalize by row sum at the end.
// ---------------------------------------------------------------------------
__global__ __launch_bounds__(256) void k_attn_mma(
    const float* __restrict__ adj,   // [B,1024,1024]
    const float* __restrict__ bias,  // [96]
    float* __restrict__ out)         // [B,1024,768]
{
    extern __shared__ __align__(16) char ds[];
    const int tid = threadIdx.x;
    const int wid = tid >> 5, lane = tid & 31;
    const int g   = lane >> 2, tig = lane & 3;
    const int wm  = wid & 3, wn = wid >> 2;
    const int bh  = blockIdx.x, batch = bh >> 3, h = bh & 7;
    const int i0  = blockIdx.y * 128;

    float* adst_s = (float*)(ds + SM2_ADST);
    for (int j = tid; j < 1024; j += 256)
        adst_s[j] = g_adst[(size_t)bh * 1024 + j];

    const int pi = tid >> 1, phalf = tid & 1;
    const float asr = g_asrc[(size_t)bh * 1024 + i0 + pi];
    const float* adjrow = adj + ((size_t)batch * 1024 + i0 + pi) * 1024;
    float ssum = 0.f;

    float acc[2][6][4];
#pragma unroll
    for (int ma = 0; ma < 2; ++ma)
#pragma unroll
        for (int na = 0; na < 6; ++na)
#pragma unroll
            for (int q = 0; q < 4; ++q) acc[ma][na][q] = 0.f;

    const uint4* __restrict__ Hh4 = (const uint4*)g_hTh;
    const uint4* __restrict__ Hl4 = (const uint4*)g_hTl;
    __syncthreads();

    for (int j0 = 0; j0 < 1024; j0 += 32) {
        // h^T tiles: 96 o-rows x 32 j (4 uint4/row), hi+lo
#pragma unroll
        for (int it = 0; it < 2; ++it) {
            int idx = tid + it * 256;
            if (idx < 384) {
                int r = idx >> 2, c = idx & 3;
                int src = (bh * 96 + r) * 128 + (j0 >> 3) + c;
                *(uint4*)(ds + SM2_HH + r * 80 + c * 16) = Hh4[src];
                *(uint4*)(ds + SM2_HL + r * 80 + c * 16) = Hl4[src];
            }
        }
        // p tile: 128 i x 32 j, unnormalized exp, bf16 split
#pragma unroll
        for (int q = 0; q < 4; ++q) {
            int j = j0 + phalf * 16 + q * 4;
            float4 av = *(const float4*)(adjrow + j);
            float ap[4] = {av.x, av.y, av.z, av.w};
            float pv[4];
#pragma unroll
            for (int t = 0; t < 4; ++t) {
                float l = asr + adst_s[j + t];
                l = l >= 0.f ? l : LEAKY * l;
                l = (ap[t] == 0.f) ? -999.f : l;
                float p = __expf(l);
                ssum += p;
                pv[t] = p;
            }
            __nv_bfloat16 b0 = __float2bfloat16(pv[0]);
            __nv_bfloat16 b1 = __float2bfloat16(pv[1]);
            __nv_bfloat16 b2 = __float2bfloat16(pv[2]);
            __nv_bfloat16 b3 = __float2bfloat16(pv[3]);
            int off = pi * 80 + (phalf * 16 + q * 4) * 2;
            *(uint32_t*)(ds + SM2_PH + off)     = pack_bf2(pv[0], pv[1]);
            *(uint32_t*)(ds + SM2_PH + off + 4) = pack_bf2(pv[2], pv[3]);
            *(uint32_t*)(ds + SM2_PL + off)     =
                pack_bf2(pv[0] - __bfloat162float(b0), pv[1] - __bfloat162float(b1));
            *(uint32_t*)(ds + SM2_PL + off + 4) =
                pack_bf2(pv[2] - __bfloat162float(b2), pv[3] - __bfloat162float(b3));
        }
        __syncthreads();
#pragma unroll
        for (int ks = 0; ks < 2; ++ks) {
            const int kb = ks * 32;
            uint32_t ahi[2][4], alo[2][4];
#pragma unroll
            for (int ma = 0; ma < 2; ++ma) {
                int rb = wm * 32 + ma * 16;
                ahi[ma][0] = *(const uint32_t*)(ds + SM2_PH + (rb + g)     * 80 + kb + tig * 4);
                ahi[ma][1] = *(const uint32_t*)(ds + SM2_PH + (rb + g + 8) * 80 + kb + tig * 4);
                ahi[ma][2] = *(const uint32_t*)(ds + SM2_PH + (rb + g)     * 80 + kb + 16 + tig * 4);
                ahi[ma][3] = *(const uint32_t*)(ds + SM2_PH + (rb + g + 8) * 80 + kb + 16 + tig * 4);
                alo[ma][0] = *(const uint32_t*)(ds + SM2_PL + (rb + g)     * 80 + kb + tig * 4);
                alo[ma][1] = *(const uint32_t*)(ds + SM2_PL + (rb + g + 8) * 80 + kb + tig * 4);
                alo[ma][2] = *(const uint32_t*)(ds + SM2_PL + (rb + g)     * 80 + kb + 16 + tig * 4);
                alo[ma][3] = *(const uint32_t*)(ds + SM2_PL + (rb + g + 8) * 80 + kb + 16 + tig * 4);
            }
#pragma unroll
            for (int na = 0; na < 6; ++na) {
                int n = wn * 48 + na * 8 + g;
                uint32_t bhi[2], blo[2];
                bhi[0] = *(const uint32_t*)(ds + SM2_HH + n * 80 + kb + tig * 4);
                bhi[1] = *(const uint32_t*)(ds + SM2_HH + n * 80 + kb + 16 + tig * 4);
                blo[0] = *(const uint32_t*)(ds + SM2_HL + n * 80 + kb + tig * 4);
                blo[1] = *(const uint32_t*)(ds + SM2_HL + n * 80 + kb + 16 + tig * 4);
#pragma unroll
                for (int ma = 0; ma < 2; ++ma) {
                    mma16816(acc[ma][na], ahi[ma], bhi);
                    mma16816(acc[ma][na], ahi[ma], blo);
                    mma16816(acc[ma][na], alo[ma], bhi);
                }
            }
        }
        __syncthreads();
    }

    // row sums
    ssum += __shfl_xor_sync(0xffffffffu, ssum, 1);
    float* ss = (float*)(ds + SM2_SS);
    if (phalf == 0) ss[pi] = ssum;
    __syncthreads();

    // stage accumulators (overlays operand tiles; all consumed)
    float* dtile = (float*)ds;
#pragma unroll
    for (int ma = 0; ma < 2; ++ma)
#pragma unroll
        for (int na = 0; na < 6; ++na) {
            int rb = wm * 32 + ma * 16 + g;
            int cb = wn * 48 + na * 8 + 2 * tig;
            dtile[rb * 97 + cb]           = acc[ma][na][0];
            dtile[rb * 97 + cb + 1]       = acc[ma][na][1];
            dtile[(rb + 8) * 97 + cb]     = acc[ma][na][2];
            dtile[(rb + 8) * 97 + cb + 1] = acc[ma][na][3];
        }
    __syncthreads();

    // normalize + bias + elu, coalesced scatter to [b,n,h*96+o]
    for (int i = tid; i < 128 * 96; i += 256) {
        int r = i / 96, c = i - r * 96;
        float v = dtile[r * 97 + c] * (1.f / ss[r]) + __ldg(&bias[c]);
        v = v > 0.f ? v : expm1f(v);
        out[((size_t)batch * 1024 + i0 + r) * 768 + h * 96 + c] = v;
    }
}

// ---------------------------------------------------------------------------
// Kernel 3 (HMMA): gate GEMM feat_in @ Hw^T + Hb -> sigmoid -> blend in-place.
// ---------------------------------------------------------------------------
__global__ __launch_bounds__(256) void k_gate_mma(
    const float* __restrict__ X, const float* __restrict__ Hb,
    float* __restrict__ out)
{
    extern __shared__ __align__(16) char ds[];
    const int tid  = threadIdx.x;
    const int wid  = tid >> 5, lane = tid & 31;
    const int g    = lane >> 2, tig = lane & 3;
    const int wm   = wid & 3, wn = wid >> 2;
    const int row0 = blockIdx.x * 128, c0 = blockIdx.y * 96;

    float* hbv = (float*)(ds + SM_VEC);
    if (tid < 96) hbv[tid] = Hb[c0 + tid];

    float acc[2][6][4];
#pragma unroll
    for (int ma = 0; ma < 2; ++ma)
#pragma unroll
        for (int na = 0; na < 6; ++na)
#pragma unroll
            for (int q = 0; q < 4; ++q) acc[ma][na][q] = 0.f;

    const uint4* __restrict__ Ah4 = (const uint4*)g_Ah;
    const uint4* __restrict__ Al4 = (const uint4*)g_Al;
    const uint4* __restrict__ Wh4 = (const uint4*)g_Hwh;
    const uint4* __restrict__ Wl4 = (const uint4*)g_Hwl;

    for (int ch = 0; ch < 24; ++ch) {
#pragma unroll
        for (int it = 0; it < 2; ++it) {
            int idx = tid + it * 256;
            int r = idx >> 2, c = idx & 3;
            int src = (row0 + r) * 96 + ch * 4 + c;
            *(uint4*)(ds + SM_AH + r * 80 + c * 16) = Ah4[src];
            *(uint4*)(ds + SM_AL + r * 80 + c * 16) = Al4[src];
        }
#pragma unroll
        for (int it = 0; it < 2; ++it) {
            int idx = tid + it * 256;
            if (idx < 384) {
                int r = idx >> 2, c = idx & 3;
                int src = (c0 + r) * 96 + ch * 4 + c;
                *(uint4*)(ds + SM_WH + r * 80 + c * 16) = Wh4[src];
                *(uint4*)(ds + SM_WL + r * 80 + c * 16) = Wl4[src];
            }
        }
        __syncthreads();
#pragma unroll
        for (int ks = 0; ks < 2; ++ks) {
            const int kb = ks * 32;
            uint32_t ahi[2][4], alo[2][4];
#pragma unroll
            for (int ma = 0; ma < 2; ++ma) {
                int rb = wm * 32 + ma * 16;
                ahi[ma][0] = *(const uint32_t*)(ds + SM_AH + (rb + g)     * 80 + kb + tig * 4);
                ahi[ma][1] = *(const uint32_t*)(ds + SM_AH + (rb + g + 8) * 80 + kb + tig * 4);
                ahi[ma][2] = *(const uint32_t*)(ds + SM_AH + (rb + g)     * 80 + kb + 16 + tig * 4);
                ahi[ma][3] = *(const uint32_t*)(ds + SM_AH + (rb + g + 8) * 80 + kb + 16 + tig * 4);
                alo[ma][0] = *(const uint32_t*)(ds + SM_AL + (rb + g)     * 80 + kb + tig * 4);
                alo[ma][1] = *(const uint32_t*)(ds + SM_AL + (rb + g + 8) * 80 + kb + tig * 4);
                alo[ma][2] = *(const uint32_t*)(ds + SM_AL + (rb + g)     * 80 + kb + 16 + tig * 4);
                alo[ma][3] = *(const uint32_t*)(ds + SM_AL + (rb + g + 8) * 80 + kb + 16 + tig * 4);
            }
#pragma unroll
            for (int na = 0; na < 6; ++na) {
                int n = wn * 48 + na * 8 + g;
                uint32_t bhi[2], blo[2];
                bhi[0] = *(const uint32_t*)(ds + SM_WH + n * 80 + kb + tig * 4);
                bhi[1] = *(const uint32_t*)(ds + SM_WH + n * 80 + kb + 16 + tig * 4);
                blo[0] = *(const uint32_t*)(ds + SM_WL + n * 80 + kb + tig * 4);
                blo[1] = *(const uint32_t*)(ds + SM_WL + n * 80 + kb + 16 + tig * 4);
#pragma unroll
                for (int ma = 0; ma < 2; ++ma) {
                    mma16816(acc[ma][na], ahi[ma], bhi);
                    mma16816(acc[ma][na], ahi[ma], blo);
                    mma16816(acc[ma][na], alo[ma], bhi);
                }
            }
        }
        __syncthreads();
    }

    float* dtile = (float*)(ds + SM_DT);
#pragma unroll
    for (int ma = 0; ma < 2; ++ma)
#pragma unroll
        for (int na = 0; na < 6; ++na) {
            int rb = wm * 32 + ma * 16 + g;
            int cb = wn * 48 + na * 8 + 2 * tig;
            dtile[rb * 97 + cb]           = acc[ma][na][0];
            dtile[rb * 97 + cb + 1]       = acc[ma][na][1];
            dtile[(rb + 8) * 97 + cb]     = acc[ma][na][2];
            dtile[(rb + 8) * 97 + cb + 1] = acc[ma][na][3];
        }
    __syncthreads();

    for (int i = tid; i < 128 * 96; i += 256) {
        int r = i / 96, c = i - r * 96;
        int row = row0 + r, col = c0 + c;
        float v = dtile[r * 97 + c];
        float gg = 1.f / (1.f + __expf(-(v + hbv[c])));
        size_t idx = (size_t)row * 768 + col;
        float fo = out[idx], xi = X[idx];
        out[idx] = fmaf(gg, fo - xi, xi);
    }
}

// ---------------------------------------------------------------------------
// Inputs (metadata order): feat_in, adj, W, b, w_src, w_dst, Hw, Hb
// ---------------------------------------------------------------------------
extern "C" void kernel_launch(void* const* d_in, const int* in_sizes, int n_in,
                              void* d_out, int out_size)
{
    const float* feat_in = (const float*)d_in[0];
    const float* adj     = (const float*)d_in[1];
    const float* W       = (const float*)d_in[2];
    const float* bias    = (const float*)d_in[3];
    const float* wsrc    = (const float*)d_in[4];
    const float* wdst    = (const float*)d_in[5];
    const float* Hw      = (const float*)d_in[6];
    const float* Hb      = (const float*)d_in[7];
    float* out           = (float*)d_out;
    (void)in_sizes; (void)n_in; (void)out_size;

    static bool attr_done = false;
    if (!attr_done) {
        cudaFuncSetAttribute(k_proj_mma, cudaFuncAttributeMaxDynamicSharedMemorySize, SM_TOT);
        cudaFuncSetAttribute(k_attn_mma, cudaFuncAttributeMaxDynamicSharedMemorySize, SM2_TOT);
        cudaFuncSetAttribute(k_gate_mma, cudaFuncAttributeMaxDynamicSharedMemorySize, SM_TOT);
        attr_done = true;
    }

    k_prep_a<<<(8192 * 768 + 255) / 256, 256>>>(feat_in, Hw);
    k_prep_w<<<(8 * 96 * 768 + 255) / 256, 256>>>(W);
    k_proj_mma<<<dim3(64, 8), 256, SM_TOT>>>(wsrc, wdst);
    k_attn_mma<<<dim3(64, 8), 256, SM2_TOT>>>(adj, bias, out);
    k_gate_mma<<<dim3(64, 8), 256, SM_TOT>>>(feat_in, Hb, out);
}